// round 1
// baseline (speedup 1.0000x reference)
#include <cuda_runtime.h>

#define IMG      384
#define W_OUT    52          // output columns per tile
#define TILE_H   32          // output rows per tile
#define ROWS_PT  16          // rows per thread, vertical pass
#define SV_STRIDE 68         // padded smem col count (bank-conflict free)
#define SMEM_BYTES (TILE_H * SV_STRIDE * 2 * (int)sizeof(float4))  // 69632

__device__ __forceinline__ float4 f4z() { return make_float4(0.f, 0.f, 0.f, 0.f); }

__global__ __launch_bounds__(256, 3)
void gauss13_kernel(const float* __restrict__ in, float* __restrict__ out)
{
    // Normalized 1D gaussian, sigma=2, ws=13 (literals -> FFMA-imm form)
    const float W[13] = {
        0.0022181959f, 0.0087731350f, 0.0270231560f, 0.0648251852f,
        0.1211093910f, 0.1762131227f, 0.1996756275f, 0.1762131227f,
        0.1211093910f, 0.0648251852f, 0.0270231560f, 0.0087731350f,
        0.0022181959f };

    extern __shared__ float4 sV[];   // [TILE_H][SV_STRIDE][2] : vertically blurred tile

    const int z  = blockIdx.z;
    const int n  = z >> 1;           // batch index
    const int p  = z & 1;            // channel half (channels 0-7 or 8-15)
    const int x0 = blockIdx.x * W_OUT;
    const int y0 = blockIdx.y * TILE_H;

    const float4* __restrict__ ibase =
        reinterpret_cast<const float4*>(in) + (size_t)n * (IMG * IMG * 4) + p * 2;
    float4* __restrict__ obase =
        reinterpret_cast<float4*>(out) + (size_t)n * (IMG * IMG * 4) + p * 2;

    // ---------------- vertical pass (global -> smem), register ring ----------------
    {
        const int tx  = threadIdx.x;      // 0..127
        const int col = tx >> 1;          // 0..63 (loaded column incl. halo)
        const int cq  = tx & 1;           // which float4 of this channel half
        const int gw  = x0 - 6 + col;     // global column
        const bool wok = ((unsigned)gw < (unsigned)IMG);
        const int r0  = y0 + (int)threadIdx.y * ROWS_PT - 6;  // first loaded row
        const float4* cb = ibase + cq;

        float4 win[13];
        #pragma unroll
        for (int i = 0; i < 12; ++i) {
            int h = r0 + i;
            win[i] = (wok && (unsigned)h < (unsigned)IMG)
                   ? __ldg(cb + ((size_t)h * IMG + gw) * 4) : f4z();
        }
        #pragma unroll
        for (int r = 0; r < ROWS_PT; ++r) {
            int h = r0 + 12 + r;
            win[(r + 12) % 13] = (wok && (unsigned)h < (unsigned)IMG)
                   ? __ldg(cb + ((size_t)h * IMG + gw) * 4) : f4z();
            float4 a = f4z();
            #pragma unroll
            for (int k = 0; k < 13; ++k) {
                float4 v = win[(r + k) % 13];
                a.x = fmaf(W[k], v.x, a.x);
                a.y = fmaf(W[k], v.y, a.y);
                a.z = fmaf(W[k], v.z, a.z);
                a.w = fmaf(W[k], v.w, a.w);
            }
            sV[(((threadIdx.y * ROWS_PT + r) * SV_STRIDE) + col) * 2 + cq] = a;
        }
    }
    __syncthreads();

    // ---------------- horizontal pass (smem -> global), streaming accumulators ----
    {
        const int tid  = (int)threadIdx.y * 128 + (int)threadIdx.x;  // 0..255
        const int cq   = tid & 1;
        const int seg  = (tid >> 1) & 3;   // output col = seg + 4*i
        const int hrow = tid >> 3;         // 0..31

        float4 acc[13];
        #pragma unroll
        for (int i = 0; i < 13; ++i) acc[i] = f4z();

        #pragma unroll
        for (int c = 0; c < 61; ++c) {
            float4 v = sV[((hrow * SV_STRIDE) + seg + c) * 2 + cq];
            #pragma unroll
            for (int i = 0; i < 13; ++i) {
                int k = c - 4 * i;
                if (k >= 0 && k < 13) {     // compile-time pruned
                    acc[i].x = fmaf(W[k], v.x, acc[i].x);
                    acc[i].y = fmaf(W[k], v.y, acc[i].y);
                    acc[i].z = fmaf(W[k], v.z, acc[i].z);
                    acc[i].w = fmaf(W[k], v.w, acc[i].w);
                }
            }
        }

        const int gy = y0 + hrow;
        float4* ob = obase + cq;
        #pragma unroll
        for (int i = 0; i < 13; ++i) {
            int gx = x0 + seg + 4 * i;
            if (gx < IMG)
                ob[((size_t)gy * IMG + gx) * 4] = acc[i];
        }
    }
}

extern "C" void kernel_launch(void* const* d_in, const int* in_sizes, int n_in,
                              void* d_out, int out_size)
{
    (void)in_sizes; (void)n_in; (void)out_size;
    const float* x = (const float*)d_in[0];
    float* y = (float*)d_out;

    cudaFuncSetAttribute(gauss13_kernel,
                         cudaFuncAttributeMaxDynamicSharedMemorySize, SMEM_BYTES);

    dim3 grid(8 /* ceil(384/52) */, IMG / TILE_H /* 12 */, 32 * 2 /* n * channel-halves */);
    dim3 block(128, 2);
    gauss13_kernel<<<grid, block, SMEM_BYTES>>>(x, y);
}

// round 2
// speedup vs baseline: 1.4700x; 1.4700x over previous
#include <cuda_runtime.h>
#include <cuda_fp16.h>

#define IMG      384
#define W_OUT    52          // output columns per tile
#define TILE_H   32          // output rows per tile
#define ROWS_PT  16          // rows per thread, vertical pass
#define S_PIX    68          // padded pixel stride (row stride = 68*16B -> 16 words mod 32: conflict-free)
#define SMEM_BYTES (TILE_H * S_PIX * 16)   // 34816 B (each pixel = 8 channels fp16 = 16 B)

__device__ __forceinline__ float4 f4z() { return make_float4(0.f, 0.f, 0.f, 0.f); }

union H2U { __half2 h; unsigned u; };

__global__ __launch_bounds__(256, 3)
void gauss13_kernel(const float* __restrict__ in, float* __restrict__ out)
{
    // Normalized 1D gaussian, sigma=2, ws=13 (literals -> FFMA-imm form)
    const float W[13] = {
        0.0022181959f, 0.0087731350f, 0.0270231560f, 0.0648251852f,
        0.1211093910f, 0.1762131227f, 0.1996756275f, 0.1762131227f,
        0.1211093910f, 0.0648251852f, 0.0270231560f, 0.0087731350f,
        0.0022181959f };

    // smem: [TILE_H][S_PIX][2 cq] of half4 (8 B) -> view as uint2
    extern __shared__ uint2 sV[];

    const int z  = blockIdx.z;
    const int n  = z >> 1;           // batch index
    const int p  = z & 1;            // channel half (channels 0-7 or 8-15)
    const int x0 = blockIdx.x * W_OUT;
    const int y0 = blockIdx.y * TILE_H;

    const float4* __restrict__ ibase =
        reinterpret_cast<const float4*>(in) + (size_t)n * (IMG * IMG * 4) + p * 2;
    float4* __restrict__ obase =
        reinterpret_cast<float4*>(out) + (size_t)n * (IMG * IMG * 4) + p * 2;

    // ---------------- vertical pass (global -> smem fp16), register ring ----------------
    {
        const int tx  = threadIdx.x;      // 0..127
        const int col = tx >> 1;          // 0..63 (loaded column incl. halo)
        const int cq  = tx & 1;           // which float4 of this channel half
        const int gw  = x0 - 6 + col;     // global column
        const bool wok = ((unsigned)gw < (unsigned)IMG);
        const int r0  = y0 + (int)threadIdx.y * ROWS_PT - 6;  // first loaded row
        const float4* cb = ibase + cq;

        float4 win[13];
        #pragma unroll
        for (int i = 0; i < 12; ++i) {
            int h = r0 + i;
            win[i] = (wok && (unsigned)h < (unsigned)IMG)
                   ? __ldg(cb + ((size_t)h * IMG + gw) * 4) : f4z();
        }
        #pragma unroll
        for (int r = 0; r < ROWS_PT; ++r) {
            int h = r0 + 12 + r;
            win[(r + 12) % 13] = (wok && (unsigned)h < (unsigned)IMG)
                   ? __ldg(cb + ((size_t)h * IMG + gw) * 4) : f4z();
            float4 a = f4z();
            #pragma unroll
            for (int k = 0; k < 13; ++k) {
                float4 v = win[(r + k) % 13];
                a.x = fmaf(W[k], v.x, a.x);
                a.y = fmaf(W[k], v.y, a.y);
                a.z = fmaf(W[k], v.z, a.z);
                a.w = fmaf(W[k], v.w, a.w);
            }
            // pack to fp16 (single rounding), store 8 B
            H2U u0, u1;
            u0.h = __floats2half2_rn(a.x, a.y);
            u1.h = __floats2half2_rn(a.z, a.w);
            uint2 pk; pk.x = u0.u; pk.y = u1.u;
            sV[((threadIdx.y * ROWS_PT + r) * S_PIX + col) * 2 + cq] = pk;
        }
    }
    __syncthreads();

    // ---------------- horizontal pass (smem fp16 -> global f32) -------------------------
    {
        const int tid  = (int)threadIdx.y * 128 + (int)threadIdx.x;  // 0..255
        const int cq   = tid & 1;
        const int seg  = (tid >> 1) & 3;   // output col = seg + 4*i
        const int hrow = tid >> 3;         // 0..31

        float4 acc[13];
        #pragma unroll
        for (int i = 0; i < 13; ++i) acc[i] = f4z();

        const uint2* rowp = sV + (hrow * S_PIX) * 2 + cq;

        #pragma unroll
        for (int c = 0; c < 61; ++c) {
            uint2 pk = rowp[(seg + c) * 2];
            H2U u0, u1; u0.u = pk.x; u1.u = pk.y;
            float2 f01 = __half22float2(u0.h);
            float2 f23 = __half22float2(u1.h);
            #pragma unroll
            for (int i = 0; i < 13; ++i) {
                int k = c - 4 * i;
                if (k >= 0 && k < 13) {     // compile-time pruned
                    acc[i].x = fmaf(W[k], f01.x, acc[i].x);
                    acc[i].y = fmaf(W[k], f01.y, acc[i].y);
                    acc[i].z = fmaf(W[k], f23.x, acc[i].z);
                    acc[i].w = fmaf(W[k], f23.y, acc[i].w);
                }
            }
        }

        const int gy = y0 + hrow;
        float4* ob = obase + cq;
        #pragma unroll
        for (int i = 0; i < 13; ++i) {
            int gx = x0 + seg + 4 * i;
            if (gx < IMG)
                ob[((size_t)gy * IMG + gx) * 4] = acc[i];
        }
    }
}

extern "C" void kernel_launch(void* const* d_in, const int* in_sizes, int n_in,
                              void* d_out, int out_size)
{
    (void)in_sizes; (void)n_in; (void)out_size;
    const float* x = (const float*)d_in[0];
    float* y = (float*)d_out;

    cudaFuncSetAttribute(gauss13_kernel,
                         cudaFuncAttributeMaxDynamicSharedMemorySize, SMEM_BYTES);

    dim3 grid(8 /* ceil(384/52) */, IMG / TILE_H /* 12 */, 32 * 2 /* n * channel-halves */);
    dim3 block(128, 2);
    gauss13_kernel<<<grid, block, SMEM_BYTES>>>(x, y);
}